// round 1
// baseline (speedup 1.0000x reference)
#include <cuda_runtime.h>

// y = min(((x + 1) * 0.75)^2, 10)  — elementwise over 8192*8192 fp32.
// Pure HBM-bound streaming kernel: float4 vectorized, one quad per thread.

__device__ __forceinline__ float f(float x) {
    float t = (x + 1.0f) * 0.75f;
    float y = t * t;
    return fminf(y, 10.0f);
}

__global__ __launch_bounds__(256) void elemwise_kernel(const float4* __restrict__ in,
                                                       float4* __restrict__ out,
                                                       int n4) {
    int i = blockIdx.x * blockDim.x + threadIdx.x;
    if (i < n4) {
        float4 v = in[i];
        float4 r;
        r.x = f(v.x);
        r.y = f(v.y);
        r.z = f(v.z);
        r.w = f(v.w);
        out[i] = r;
    }
}

extern "C" void kernel_launch(void* const* d_in, const int* in_sizes, int n_in,
                              void* d_out, int out_size) {
    const float4* in = (const float4*)d_in[0];
    float4* out = (float4*)d_out;
    int n = in_sizes[0];          // 8192*8192 = 67108864, divisible by 4
    int n4 = n / 4;               // 16777216
    int threads = 256;
    int blocks = (n4 + threads - 1) / threads;  // 65536
    elemwise_kernel<<<blocks, threads>>>(in, out, n4);
}

// round 2
// speedup vs baseline: 1.0043x; 1.0043x over previous
#include <cuda_runtime.h>

// y = min(((x + 1) * 0.75)^2, 10)  — elementwise over 8192*8192 fp32.
// HBM-bound streaming: 4 independent float4 loads per thread (MLP_p1=4),
// coalesced at blockDim stride. 67108864 elems = 16384 blocks * 256 thr * 16 elems.

#define VPT 4  // float4 vectors per thread

__device__ __forceinline__ float f(float x) {
    float t = (x + 1.0f) * 0.75f;
    float y = t * t;
    return fminf(y, 10.0f);
}

__device__ __forceinline__ float4 f4(float4 v) {
    float4 r;
    r.x = f(v.x); r.y = f(v.y); r.z = f(v.z); r.w = f(v.w);
    return r;
}

__global__ __launch_bounds__(256) void elemwise_kernel(const float4* __restrict__ in,
                                                       float4* __restrict__ out) {
    // base index for this thread's first vector
    unsigned base = blockIdx.x * (blockDim.x * VPT) + threadIdx.x;

    // Front-batch all loads (independent -> MLP=4), then compute, then store.
    float4 v0 = in[base + 0u * 256u];
    float4 v1 = in[base + 1u * 256u];
    float4 v2 = in[base + 2u * 256u];
    float4 v3 = in[base + 3u * 256u];

    out[base + 0u * 256u] = f4(v0);
    out[base + 1u * 256u] = f4(v1);
    out[base + 2u * 256u] = f4(v2);
    out[base + 3u * 256u] = f4(v3);
}

extern "C" void kernel_launch(void* const* d_in, const int* in_sizes, int n_in,
                              void* d_out, int out_size) {
    const float4* in = (const float4*)d_in[0];
    float4* out = (float4*)d_out;
    int n = in_sizes[0];                 // 67108864
    int n4 = n / 4;                      // 16777216 float4s
    int threads = 256;
    int blocks = n4 / (threads * VPT);   // 16384, exact
    elemwise_kernel<<<blocks, threads>>>(in, out);
}